// round 8
// baseline (speedup 1.0000x reference)
#include <cuda_runtime.h>

// ---------------------------------------------------------------------------
// Photonic Clements mesh, N=128. 256x128 complex state; columns independent.
//
// ROUND 8: TWO WARPS PER COLUMN (64 threads). Lane L (0..63) owns rows
// 4L..4L+3 as pairs (a0,b0)=(rows 4L,4L+1), (a1,b1)=(rows 4L+2,4L+3).
// Halves per-warp instructions vs the 27.4us one-warp round-5 kernel.
//   D layer k : a0 *= e^{i th[k][2L]}, a1 *= e^{i th[k][2L+1]}
//   M         : lane-local MIX(a0,b0), MIX(a1,b1)
//   X         : MIX(b0,a1) lane-local; boundary (b1, next-lane a0) via shfl,
//               except the single cross-warp boundary (L=31/32) via 2 smem
//               slots + one 2-warp __syncthreads (parity double-buffered).
// Corners: row 0 (L=0 a0), row 255 (L=63 b1) scale by aX*sqrt(1-CT).
// Output serialization identical to rounds 4-7 (mode on out_size).
// ---------------------------------------------------------------------------

#define NCOLS   128
#define NLAYERS 255
#define FULL    0xffffffffu

#define AM_  0.97467943448089633f    // sqrt(1-0.05)
#define PP_  0.71063352017759484f    // sqrt(0.5+0.005)
#define QQ_  0.70356236397351441f    // sqrt(0.5-0.005)
#define AMP_ (AM_*PP_)               // A (MMI)
#define AMQ_ (AM_*QQ_)               // B (MMI)
#define AX_  0.98994949366116653f    // sqrt(1-0.02)
#define XC_  (AX_*0.1f)                       // aX*sqrt(CT)
#define XS_  (AX_*0.99498743710661995f)       // aX*sqrt(1-CT), corner scalar

// phase table: float4 [layer k][L] = (cos th[k][2L], sin th[k][2L],
//                                     cos th[k][2L+1], sin th[k][2L+1])
__device__ float4 g_ph4[NLAYERS * 64];

__global__ void phase_kernel(const float* __restrict__ theta_even) {
    int i = blockIdx.x * blockDim.x + threadIdx.x;
    if (i < NLAYERS * NCOLS) {
        float s, c;
        sincosf(theta_even[i], &s, &c);
        reinterpret_cast<float2*>(g_ph4)[i] = make_float2(c, s);
    }
}

// v *= (c + i s)
#define CMUL(v, c_, s_) do { \
    float _nx = fmaf((v).x, (c_), -(v).y * (s_)); \
    float _ny = fmaf((v).x, (s_),  (v).y * (c_)); \
    (v).x = _nx; (v).y = _ny; } while (0)

// [a;b] <- [[A,iB],[iB,A]][a;b]
#define MIX(a, b, A, B) do { \
    float _ar = fmaf((A), (a).x, -(B) * (b).y); \
    float _ai = fmaf((A), (a).y,  (B) * (b).x); \
    float _br = fmaf((A), (b).x, -(B) * (a).y); \
    float _bi = fmaf((A), (b).y,  (B) * (a).x); \
    (a).x = _ar; (a).y = _ai; (b).x = _br; (b).y = _bi; } while (0)

// one D+M stage from packed phases q = (c0,s0,c1,s1)
#define STAGE(q) do { \
    CMUL(a0, (q).x, (q).y); \
    CMUL(a1, (q).z, (q).w); \
    MIX(a0, b0, AMP_, AMQ_); \
    MIX(a1, b1, AMP_, AMQ_); } while (0)

// CROSS step; par is a compile-time 0/1 smem parity
#define XSTEP(par) do { \
    if (L == 32) sA[par] = a0;          /* row 128 -> needed by L=31 */ \
    if (L == 31) sB[par] = b1;          /* row 127 -> needed by L=32 */ \
    float _nax = __shfl_down_sync(FULL, a0.x, 1);  /* next lane a0 = row 4L+4 */ \
    float _nay = __shfl_down_sync(FULL, a0.y, 1); \
    float _pbx = __shfl_up_sync  (FULL, b1.x, 1);  /* prev lane b1 = row 4L-1 */ \
    float _pby = __shfl_up_sync  (FULL, b1.y, 1); \
    __syncthreads(); \
    if (L == 31) { _nax = sA[par].x; _nay = sA[par].y; } \
    if (L == 32) { _pbx = sB[par].x; _pby = sB[par].y; } \
    MIX(b0, a1, XC_, XS_);              /* pair (4L+1, 4L+2) */ \
    float _n1x = fmaf(XC_, b1.x, -XS_ * _nay);   /* b1' = XC b1 + iXS a0next */ \
    float _n1y = fmaf(XC_, b1.y,  XS_ * _nax); \
    float _n0x = fmaf(XC_, a0.x, -XS_ * _pby);   /* a0' = XC a0 + iXS b1prev */ \
    float _n0y = fmaf(XC_, a0.y,  XS_ * _pbx); \
    b1.x = (L < 63) ? _n1x : XS_ * b1.x;   /* row 255 corner */ \
    b1.y = (L < 63) ? _n1y : XS_ * b1.y; \
    a0.x = (L > 0)  ? _n0x : XS_ * a0.x;   /* row 0 corner */ \
    a0.y = (L > 0)  ? _n0y : XS_ * a0.y; } while (0)

__global__ void __launch_bounds__(64, 1)
mesh_kernel(const float* __restrict__ theta_in,
            const float* __restrict__ theta_out,
            float* __restrict__ out,
            int mode)   // 1 = real-only (16384 floats), 2 = planar (32768 floats)
{
    __shared__ float2 sA[2], sB[2];   // cross-warp boundary, parity buffered

    const int c = blockIdx.x;    // column (input port)
    const int L = threadIdx.x;   // global lane 0..63: rows 4L..4L+3

    float2 a0 = {0.f, 0.f}, b0 = {0.f, 0.f};
    float2 a1 = {0.f, 0.f}, b1 = {0.f, 0.f};

    // --- input: rows 2c, 2c+1 of column c of MMI_IN @ diag(e^{i th_in}) ---
    {
        float s, co;
        sincosf(theta_in[c], &s, &co);
        float2 ain = make_float2( AMP_ * co, AMP_ * s);   //  aM*p * e^{i th}
        float2 bin = make_float2(-AMQ_ * s,  AMQ_ * co);  // i*aM*q * e^{i th}
        if      (2 * c == 4 * L)     { a0 = ain; b0 = bin; }
        else if (2 * c == 4 * L + 2) { a1 = ain; b1 = bin; }
    }

    // --- D0, M, X ---
    {
        float4 p = g_ph4[0 * 64 + L];
        STAGE(p);
        XSTEP(0);
    }

    // iteration j (0..125): D(2j+1), M, D(2j+2), M, X; then tail D253,M,D254.
    // distance-2 double-buffered prefetch; unroll-2 keeps slots + parity static.
    float4 s0a = g_ph4[1 * 64 + L], s0b = g_ph4[2 * 64 + L];
    float4 s1a = g_ph4[3 * 64 + L], s1b = g_ph4[4 * 64 + L];

#pragma unroll 1
    for (int j = 0; j < 126; j += 2) {
        {
            int jn = (j + 2 <= 126) ? (j + 2) : 126;   // clamp; redundant load ok
            float4 na = g_ph4[(2 * jn + 1) * 64 + L];
            float4 nb = g_ph4[(2 * jn + 2) * 64 + L];
            STAGE(s0a);
            STAGE(s0b);
            XSTEP(1);
            s0a = na; s0b = nb;
        }
        {
            int jn = (j + 3 <= 126) ? (j + 3) : 126;
            float4 na = g_ph4[(2 * jn + 1) * 64 + L];
            float4 nb = g_ph4[(2 * jn + 2) * 64 + L];
            STAGE(s1a);
            STAGE(s1b);
            XSTEP(0);
            s1a = na; s1b = nb;
        }
    }

    // --- tail: D253+M (one stage), then bare D254 (s0 holds layers 253,254) ---
    STAGE(s0a);
    CMUL(a0, s0b.x, s0b.y);
    CMUL(a1, s0b.z, s0b.w);

    // --- output rows 2L, 2L+1: MMI_OUT pair reduce, then e^{i th_out} ---
#define OUTP(va, vb, jj) do { \
        float _ox = fmaf(AMP_, (va).x, -AMQ_ * (vb).y); \
        float _oy = fmaf(AMP_, (va).y,  AMQ_ * (vb).x); \
        float _so, _co; sincosf(theta_out[jj], &_so, &_co); \
        float _re = _ox * _co - _oy * _so; \
        float _im = _ox * _so + _oy * _co; \
        if (mode == 1) { out[(jj) * NCOLS + c] = _re; } \
        else { out[(jj) * NCOLS + c] = _re; \
               out[NCOLS * NCOLS + (jj) * NCOLS + c] = _im; } } while (0)

    OUTP(a0, b0, 2 * L);
    OUTP(a1, b1, 2 * L + 1);
#undef OUTP
}

extern "C" void kernel_launch(void* const* d_in, const int* in_sizes, int n_in,
                              void* d_out, int out_size) {
    // Inputs identified by SIZE (theta_even = unique 32640-elem array;
    // theta_in precedes theta_out).
    const float* th_ev  = nullptr;
    const float* small_[2] = {nullptr, nullptr};
    int ns = 0;
    for (int i = 0; i < n_in && i < 3; i++) {
        if (in_sizes[i] > 1000) th_ev = (const float*)d_in[i];
        else if (ns < 2)        small_[ns++] = (const float*)d_in[i];
    }
    const float* th_in  = small_[0];
    const float* th_out = small_[1];

    int mode = (out_size == NCOLS * NCOLS) ? 1 : 2;  // 16384 -> real-only, else planar

    phase_kernel<<<(NLAYERS * NCOLS + 255) / 256, 256>>>(th_ev);
    mesh_kernel<<<NCOLS, 64>>>(th_in, th_out, (float*)d_out, mode);
}

// round 9
// speedup vs baseline: 1.6410x; 1.6410x over previous
#include <cuda_runtime.h>

// ---------------------------------------------------------------------------
// Photonic Clements mesh, N=128. One warp per column (the proven-optimal
// structure, round 5 = 27.4us). Lane t owns rows 8t..8t+7 as v0..v7.
//
// ROUND 9 changes vs round 5 (table + math byte-identical):
//  1. Shfl hoist: boundary pairs (v0,v1),(v6,v7) advance through D,M,D,M
//     first; the 4 CROSS shuffles issue early; middle-pair math (~70 instrs)
//     runs under the shfl latency.
//  2. 3-slot rotating prefetch (126 = 3*42): each body reloads the slot it
//     just consumed for iteration j+3 -- no per-body slot-copy MOVs.
// Output serialization identical to rounds 4-8 (mode on out_size).
// ---------------------------------------------------------------------------

#define NCOLS   128
#define NLAYERS 255
#define FULL    0xffffffffu

#define AM_  0.97467943448089633f    // sqrt(1-0.05)
#define PP_  0.71063352017759484f    // sqrt(0.5+0.005)
#define QQ_  0.70356236397351441f    // sqrt(0.5-0.005)
#define AMP_ (AM_*PP_)
#define AMQ_ (AM_*QQ_)
#define AX_  0.98994949366116653f    // sqrt(1-0.02)
#define XC_  (AX_*0.1f)                       // aX*sqrt(CT)
#define XS_  (AX_*0.99498743710661995f)       // aX*sqrt(1-CT), corner scalar

// phase table: layer k, lane t reads float4s [k*64 + 2t] and [k*64 + 2t + 1]
// (phases for theta_even ports 4t..4t+3 as (c,s) float2 pairs)
__device__ float4 g_phase4[NLAYERS * 64];

__global__ void phase_kernel(const float* __restrict__ theta_even) {
    int i = blockIdx.x * blockDim.x + threadIdx.x;
    if (i < NLAYERS * NCOLS) {
        float s, c;
        sincosf(theta_even[i], &s, &c);
        reinterpret_cast<float2*>(g_phase4)[i] = make_float2(c, s);
    }
}

// v *= (c + i s)
#define CMUL(v, c_, s_) do { \
    float _nx = fmaf((v).x, (c_), -(v).y * (s_)); \
    float _ny = fmaf((v).x, (s_),  (v).y * (c_)); \
    (v).x = _nx; (v).y = _ny; } while (0)

// [a;b] <- [[A,iB],[iB,A]][a;b]
#define MIX(a, b, A, B) do { \
    float _ar = fmaf((A), (a).x, -(B) * (b).y); \
    float _ai = fmaf((A), (a).y,  (B) * (b).x); \
    float _br = fmaf((A), (b).x, -(B) * (a).y); \
    float _bi = fmaf((A), (b).y,  (B) * (a).x); \
    (a).x = _ar; (a).y = _ai; (b).x = _br; (b).y = _bi; } while (0)

#define PH(k, h) g_phase4[(k) * 64 + 2 * t + (h)]

// One iteration: D(layer a), M, D(layer b), M, X -- boundary pairs first so
// the shuffles overlap the middle-pair math.
// A0 = PH(a,0): v0 phases in .xy, v2 in .zw.  A1 = PH(a,1): v4 .xy, v6 .zw.
#define ITER(A0, A1, B0, B1) do { \
    CMUL(v0, (A0).x, (A0).y); \
    CMUL(v6, (A1).z, (A1).w); \
    MIX(v0, v1, AMP_, AMQ_); \
    MIX(v6, v7, AMP_, AMQ_); \
    CMUL(v0, (B0).x, (B0).y); \
    CMUL(v6, (B1).z, (B1).w); \
    MIX(v0, v1, AMP_, AMQ_); \
    MIX(v6, v7, AMP_, AMQ_); \
    float _nb0x = __shfl_down_sync(FULL, v0.x, 1);   /* lane t+1's v0 = row 8t+8 */ \
    float _nb0y = __shfl_down_sync(FULL, v0.y, 1); \
    float _nb7x = __shfl_up_sync  (FULL, v7.x, 1);   /* lane t-1's v7 = row 8t-1 */ \
    float _nb7y = __shfl_up_sync  (FULL, v7.y, 1); \
    CMUL(v2, (A0).z, (A0).w); \
    CMUL(v4, (A1).x, (A1).y); \
    MIX(v2, v3, AMP_, AMQ_); \
    MIX(v4, v5, AMP_, AMQ_); \
    CMUL(v2, (B0).z, (B0).w); \
    CMUL(v4, (B1).x, (B1).y); \
    MIX(v2, v3, AMP_, AMQ_); \
    MIX(v4, v5, AMP_, AMQ_); \
    MIX(v1, v2, XC_, XS_); \
    MIX(v3, v4, XC_, XS_); \
    MIX(v5, v6, XC_, XS_); \
    float _n7x = fmaf(XC_, v7.x, -XS_ * _nb0y); \
    float _n7y = fmaf(XC_, v7.y,  XS_ * _nb0x); \
    float _n0x = fmaf(XC_, v0.x, -XS_ * _nb7y); \
    float _n0y = fmaf(XC_, v0.y,  XS_ * _nb7x); \
    v7.x = (t < 31) ? _n7x : XS_ * v7.x;   /* row 255 corner */ \
    v7.y = (t < 31) ? _n7y : XS_ * v7.y; \
    v0.x = (t > 0)  ? _n0x : XS_ * v0.x;   /* row 0 corner */ \
    v0.y = (t > 0)  ? _n0y : XS_ * v0.y; } while (0)

// reload a slot with layers (2*jn+1, 2*jn+2)
#define LD(S0, S1, S2, S3, jn) do { \
    (S0) = PH(2 * (jn) + 1, 0); (S1) = PH(2 * (jn) + 1, 1); \
    (S2) = PH(2 * (jn) + 2, 0); (S3) = PH(2 * (jn) + 2, 1); } while (0)

__global__ void __launch_bounds__(32, 1)
mesh_kernel(const float* __restrict__ theta_in,
            const float* __restrict__ theta_out,
            float* __restrict__ out,
            int mode)   // 1 = real-only (16384 floats), 2 = planar (32768 floats)
{
    const int c = blockIdx.x;    // column (input port)
    const int t = threadIdx.x;   // lane: rows 8t..8t+7

    float2 v0 = {0.f, 0.f}, v1 = {0.f, 0.f}, v2 = {0.f, 0.f}, v3 = {0.f, 0.f};
    float2 v4 = {0.f, 0.f}, v5 = {0.f, 0.f}, v6 = {0.f, 0.f}, v7 = {0.f, 0.f};

    // --- input: rows 2c, 2c+1 of column c of MMI_IN @ diag(e^{i th_in}) ---
    {
        float s, co;
        sincosf(theta_in[c], &s, &co);
        float2 ain = make_float2( AMP_ * co, AMP_ * s);   //  aM*p * e^{i th}
        float2 bin = make_float2(-AMQ_ * s,  AMQ_ * co);  // i*aM*q * e^{i th}
        int slot = 2 * c - 8 * t;
        if      (slot == 0) { v0 = ain; v1 = bin; }
        else if (slot == 2) { v2 = ain; v3 = bin; }
        else if (slot == 4) { v4 = ain; v5 = bin; }
        else if (slot == 6) { v6 = ain; v7 = bin; }
    }

    // --- first: D0, M, X (hoisted like ITER) ---
    {
        float4 p01 = PH(0, 0), p23 = PH(0, 1);
        CMUL(v0, p01.x, p01.y);
        CMUL(v6, p23.z, p23.w);
        MIX(v0, v1, AMP_, AMQ_);
        MIX(v6, v7, AMP_, AMQ_);
        float nb0x = __shfl_down_sync(FULL, v0.x, 1);
        float nb0y = __shfl_down_sync(FULL, v0.y, 1);
        float nb7x = __shfl_up_sync  (FULL, v7.x, 1);
        float nb7y = __shfl_up_sync  (FULL, v7.y, 1);
        CMUL(v2, p01.z, p01.w);
        CMUL(v4, p23.x, p23.y);
        MIX(v2, v3, AMP_, AMQ_);
        MIX(v4, v5, AMP_, AMQ_);
        MIX(v1, v2, XC_, XS_);
        MIX(v3, v4, XC_, XS_);
        MIX(v5, v6, XC_, XS_);
        float n7x = fmaf(XC_, v7.x, -XS_ * nb0y);
        float n7y = fmaf(XC_, v7.y,  XS_ * nb0x);
        float n0x = fmaf(XC_, v0.x, -XS_ * nb7y);
        float n0y = fmaf(XC_, v0.y,  XS_ * nb7x);
        v7.x = (t < 31) ? n7x : XS_ * v7.x;
        v7.y = (t < 31) ? n7y : XS_ * v7.y;
        v0.x = (t > 0)  ? n0x : XS_ * v0.x;
        v0.y = (t > 0)  ? n0y : XS_ * v0.y;
    }

    // iteration j (0..125) consumes layers 2j+1, 2j+2; virtual j=126 -> (253,254)
    // 3 rotating slots, preloaded for j = 0,1,2; each body reloads its slot
    // for j+3 (clamped to 126) right after consuming it.
    float4 s0a0, s0a1, s0b0, s0b1;
    float4 s1a0, s1a1, s1b0, s1b1;
    float4 s2a0, s2a1, s2b0, s2b1;
    LD(s0a0, s0a1, s0b0, s0b1, 0);
    LD(s1a0, s1a1, s1b0, s1b1, 1);
    LD(s2a0, s2a1, s2b0, s2b1, 2);

#pragma unroll 1
    for (int j = 0; j < 126; j += 3) {
        {
            ITER(s0a0, s0a1, s0b0, s0b1);
            int jn = (j + 3 <= 126) ? (j + 3) : 126;
            LD(s0a0, s0a1, s0b0, s0b1, jn);
        }
        {
            ITER(s1a0, s1a1, s1b0, s1b1);
            int jn = (j + 4 <= 126) ? (j + 4) : 126;
            LD(s1a0, s1a1, s1b0, s1b1, jn);
        }
        {
            ITER(s2a0, s2a1, s2b0, s2b1);
            int jn = (j + 5 <= 126) ? (j + 5) : 126;
            LD(s2a0, s2a1, s2b0, s2b1, jn);
        }
    }

    // --- tail j=126: D253, M, D254 (slot 0 holds layers 253/254) ---
    CMUL(v0, s0a0.x, s0a0.y);
    CMUL(v2, s0a0.z, s0a0.w);
    CMUL(v4, s0a1.x, s0a1.y);
    CMUL(v6, s0a1.z, s0a1.w);
    MIX(v0, v1, AMP_, AMQ_);
    MIX(v2, v3, AMP_, AMQ_);
    MIX(v4, v5, AMP_, AMQ_);
    MIX(v6, v7, AMP_, AMQ_);
    CMUL(v0, s0b0.x, s0b0.y);
    CMUL(v2, s0b0.z, s0b0.w);
    CMUL(v4, s0b1.x, s0b1.y);
    CMUL(v6, s0b1.z, s0b1.w);

    // --- output rows jj = 4t..4t+3: MMI_OUT pair reduce, then e^{i th_out} ---
#define OUTP(va, vb, jj) do { \
        float _ox = fmaf(AMP_, (va).x, -AMQ_ * (vb).y); \
        float _oy = fmaf(AMP_, (va).y,  AMQ_ * (vb).x); \
        float _so, _co; sincosf(theta_out[jj], &_so, &_co); \
        float _re = _ox * _co - _oy * _so; \
        float _im = _ox * _so + _oy * _co; \
        if (mode == 1) { out[(jj) * NCOLS + c] = _re; } \
        else { out[(jj) * NCOLS + c] = _re; \
               out[NCOLS * NCOLS + (jj) * NCOLS + c] = _im; } } while (0)

    OUTP(v0, v1, 4 * t);
    OUTP(v2, v3, 4 * t + 1);
    OUTP(v4, v5, 4 * t + 2);
    OUTP(v6, v7, 4 * t + 3);
#undef OUTP
}

extern "C" void kernel_launch(void* const* d_in, const int* in_sizes, int n_in,
                              void* d_out, int out_size) {
    // Inputs identified by SIZE (theta_even = unique 32640-elem array;
    // theta_in precedes theta_out).
    const float* th_ev  = nullptr;
    const float* small_[2] = {nullptr, nullptr};
    int ns = 0;
    for (int i = 0; i < n_in && i < 3; i++) {
        if (in_sizes[i] > 1000) th_ev = (const float*)d_in[i];
        else if (ns < 2)        small_[ns++] = (const float*)d_in[i];
    }
    const float* th_in  = small_[0];
    const float* th_out = small_[1];

    int mode = (out_size == NCOLS * NCOLS) ? 1 : 2;  // 16384 -> real-only, else planar

    phase_kernel<<<(NLAYERS * NCOLS + 255) / 256, 256>>>(th_ev);
    mesh_kernel<<<NCOLS, 32>>>(th_in, th_out, (float*)d_out, mode);
}

// round 10
// speedup vs baseline: 1.6429x; 1.0011x over previous
#include <cuda_runtime.h>

// ---------------------------------------------------------------------------
// Photonic Clements mesh, N=128. One warp per column; lane t owns rows
// 8t..8t+7 as v0..v7. Round-9 structure (shfl hoist + 3-slot rotation) plus:
//  - predicate-free corners via per-lane coefficient registers
//  - pointer-strided slot reloads (immediate offsets, no per-load IMAD)
//  - peeled final trip (no clamp in the hot loop)
// Output serialization identical to rounds 4-9 (mode on out_size).
// ---------------------------------------------------------------------------

#define NCOLS   128
#define NLAYERS 255
#define FULL    0xffffffffu

#define AM_  0.97467943448089633f    // sqrt(1-0.05)
#define PP_  0.71063352017759484f    // sqrt(0.5+0.005)
#define QQ_  0.70356236397351441f    // sqrt(0.5-0.005)
#define AMP_ (AM_*PP_)
#define AMQ_ (AM_*QQ_)
#define AX_  0.98994949366116653f    // sqrt(1-0.02)
#define XC_  (AX_*0.1f)                       // aX*sqrt(CT)
#define XS_  (AX_*0.99498743710661995f)       // aX*sqrt(1-CT), corner scalar

// phase table: layer k, lane t reads float4s [k*64 + 2t] and [k*64 + 2t + 1]
__device__ float4 g_phase4[NLAYERS * 64];

__global__ void phase_kernel(const float* __restrict__ theta_even) {
    int i = blockIdx.x * blockDim.x + threadIdx.x;
    if (i < NLAYERS * NCOLS) {
        float s, c;
        sincosf(theta_even[i], &s, &c);
        reinterpret_cast<float2*>(g_phase4)[i] = make_float2(c, s);
    }
}

// v *= (c + i s)
#define CMUL(v, c_, s_) do { \
    float _nx = fmaf((v).x, (c_), -(v).y * (s_)); \
    float _ny = fmaf((v).x, (s_),  (v).y * (c_)); \
    (v).x = _nx; (v).y = _ny; } while (0)

// [a;b] <- [[A,iB],[iB,A]][a;b]
#define MIX(a, b, A, B) do { \
    float _ar = fmaf((A), (a).x, -(B) * (b).y); \
    float _ai = fmaf((A), (a).y,  (B) * (b).x); \
    float _br = fmaf((A), (b).x, -(B) * (a).y); \
    float _bi = fmaf((A), (b).y,  (B) * (a).x); \
    (a).x = _ar; (a).y = _ai; (b).x = _br; (b).y = _bi; } while (0)

// One iteration: D(a), M, D(b), M, X. Boundary pairs first; shuffles overlap
// the middle-pair math. Corners are absorbed into per-lane coeffs cA/cB
// (interior: (XC,XS); lane 31 v7 / lane 0 v0: (XS,0) -- garbage shfl x 0).
#define ITER(A0, A1, B0, B1) do { \
    CMUL(v0, (A0).x, (A0).y); \
    CMUL(v6, (A1).z, (A1).w); \
    MIX(v0, v1, AMP_, AMQ_); \
    MIX(v6, v7, AMP_, AMQ_); \
    CMUL(v0, (B0).x, (B0).y); \
    CMUL(v6, (B1).z, (B1).w); \
    MIX(v0, v1, AMP_, AMQ_); \
    MIX(v6, v7, AMP_, AMQ_); \
    float _nb0x = __shfl_down_sync(FULL, v0.x, 1);   /* lane t+1's v0 = row 8t+8 */ \
    float _nb0y = __shfl_down_sync(FULL, v0.y, 1); \
    float _nb7x = __shfl_up_sync  (FULL, v7.x, 1);   /* lane t-1's v7 = row 8t-1 */ \
    float _nb7y = __shfl_up_sync  (FULL, v7.y, 1); \
    CMUL(v2, (A0).z, (A0).w); \
    CMUL(v4, (A1).x, (A1).y); \
    MIX(v2, v3, AMP_, AMQ_); \
    MIX(v4, v5, AMP_, AMQ_); \
    CMUL(v2, (B0).z, (B0).w); \
    CMUL(v4, (B1).x, (B1).y); \
    MIX(v2, v3, AMP_, AMQ_); \
    MIX(v4, v5, AMP_, AMQ_); \
    MIX(v1, v2, XC_, XS_); \
    MIX(v3, v4, XC_, XS_); \
    MIX(v5, v6, XC_, XS_); \
    float _n7x = fmaf(cA7, v7.x, -cB7 * _nb0y); \
    float _n7y = fmaf(cA7, v7.y,  cB7 * _nb0x); \
    float _n0x = fmaf(cA0, v0.x, -cB0 * _nb7y); \
    float _n0y = fmaf(cA0, v0.y,  cB0 * _nb7x); \
    v7.x = _n7x; v7.y = _n7y; \
    v0.x = _n0x; v0.y = _n0y; } while (0)

// reload a slot from pointer p (at layer 2jn+1, lane-offset applied):
// [0],[1] = layer 2jn+1 phases; [64],[65] = layer 2jn+2 phases
#define LDP(S0, S1, S2, S3, p) do { \
    (S0) = (p)[0]; (S1) = (p)[1]; (S2) = (p)[64]; (S3) = (p)[65]; } while (0)

__global__ void __launch_bounds__(32, 1)
mesh_kernel(const float* __restrict__ theta_in,
            const float* __restrict__ theta_out,
            float* __restrict__ out,
            int mode)   // 1 = real-only (16384 floats), 2 = planar (32768 floats)
{
    const int c = blockIdx.x;    // column (input port)
    const int t = threadIdx.x;   // lane: rows 8t..8t+7

    // per-lane boundary coefficients (corners folded in, no in-loop selects)
    const float cA7 = (t < 31) ? XC_ : XS_;
    const float cB7 = (t < 31) ? XS_ : 0.f;
    const float cA0 = (t > 0)  ? XC_ : XS_;
    const float cB0 = (t > 0)  ? XS_ : 0.f;

    float2 v0 = {0.f, 0.f}, v1 = {0.f, 0.f}, v2 = {0.f, 0.f}, v3 = {0.f, 0.f};
    float2 v4 = {0.f, 0.f}, v5 = {0.f, 0.f}, v6 = {0.f, 0.f}, v7 = {0.f, 0.f};

    // --- input: rows 2c, 2c+1 of column c of MMI_IN @ diag(e^{i th_in}) ---
    {
        float s, co;
        sincosf(theta_in[c], &s, &co);
        float2 ain = make_float2( AMP_ * co, AMP_ * s);   //  aM*p * e^{i th}
        float2 bin = make_float2(-AMQ_ * s,  AMQ_ * co);  // i*aM*q * e^{i th}
        int slot = 2 * c - 8 * t;
        if      (slot == 0) { v0 = ain; v1 = bin; }
        else if (slot == 2) { v2 = ain; v3 = bin; }
        else if (slot == 4) { v4 = ain; v5 = bin; }
        else if (slot == 6) { v6 = ain; v7 = bin; }
    }

    const float4* base = g_phase4 + 2 * t;

    // --- first: D0, M, X (hoisted form) ---
    {
        float4 p01 = base[0], p23 = base[1];
        CMUL(v0, p01.x, p01.y);
        CMUL(v6, p23.z, p23.w);
        MIX(v0, v1, AMP_, AMQ_);
        MIX(v6, v7, AMP_, AMQ_);
        float nb0x = __shfl_down_sync(FULL, v0.x, 1);
        float nb0y = __shfl_down_sync(FULL, v0.y, 1);
        float nb7x = __shfl_up_sync  (FULL, v7.x, 1);
        float nb7y = __shfl_up_sync  (FULL, v7.y, 1);
        CMUL(v2, p01.z, p01.w);
        CMUL(v4, p23.x, p23.y);
        MIX(v2, v3, AMP_, AMQ_);
        MIX(v4, v5, AMP_, AMQ_);
        MIX(v1, v2, XC_, XS_);
        MIX(v3, v4, XC_, XS_);
        MIX(v5, v6, XC_, XS_);
        float n7x = fmaf(cA7, v7.x, -cB7 * nb0y);
        float n7y = fmaf(cA7, v7.y,  cB7 * nb0x);
        float n0x = fmaf(cA0, v0.x, -cB0 * nb7y);
        float n0y = fmaf(cA0, v0.y,  cB0 * nb7x);
        v7.x = n7x; v7.y = n7y;
        v0.x = n0x; v0.y = n0y;
    }

    // iteration j (0..125) consumes layers 2j+1, 2j+2; tail = D253, M, D254.
    // 3 rotating slots preloaded for j=0,1,2; per-slot pointers start at
    // jn=3,4,5 and advance by 6 layers (384 float4s) per reload.
    float4 s0a0, s0a1, s0b0, s0b1;
    float4 s1a0, s1a1, s1b0, s1b1;
    float4 s2a0, s2a1, s2b0, s2b1;
    LDP(s0a0, s0a1, s0b0, s0b1, base + 1 * 64);   // layers 1,2
    LDP(s1a0, s1a1, s1b0, s1b1, base + 3 * 64);   // layers 3,4
    LDP(s2a0, s2a1, s2b0, s2b1, base + 5 * 64);   // layers 5,6

    const float4* p0 = base + 7 * 64;    // jn=3  -> layer 7
    const float4* p1 = base + 9 * 64;    // jn=4  -> layer 9
    const float4* p2 = base + 11 * 64;   // jn=5  -> layer 11

    // 41 full trips: j = 0,3,...,120 (iters 0..122; reloads jn up to 125)
#pragma unroll 1
    for (int m = 0; m < 41; m++) {
        ITER(s0a0, s0a1, s0b0, s0b1);
        LDP(s0a0, s0a1, s0b0, s0b1, p0);
        p0 += 384;
        ITER(s1a0, s1a1, s1b0, s1b1);
        LDP(s1a0, s1a1, s1b0, s1b1, p1);
        p1 += 384;
        ITER(s2a0, s2a1, s2b0, s2b1);
        LDP(s2a0, s2a1, s2b0, s2b1, p2);
        p2 += 384;
    }

    // peeled final trip: iters 123,124,125; reload slot0 with layers 253,254
    // (p0 now points at jn=126 -> layer 253)
    ITER(s0a0, s0a1, s0b0, s0b1);
    LDP(s0a0, s0a1, s0b0, s0b1, p0);
    ITER(s1a0, s1a1, s1b0, s1b1);
    ITER(s2a0, s2a1, s2b0, s2b1);

    // --- tail: D253, M, D254 (slot 0 holds layers 253/254) ---
    CMUL(v0, s0a0.x, s0a0.y);
    CMUL(v2, s0a0.z, s0a0.w);
    CMUL(v4, s0a1.x, s0a1.y);
    CMUL(v6, s0a1.z, s0a1.w);
    MIX(v0, v1, AMP_, AMQ_);
    MIX(v2, v3, AMP_, AMQ_);
    MIX(v4, v5, AMP_, AMQ_);
    MIX(v6, v7, AMP_, AMQ_);
    CMUL(v0, s0b0.x, s0b0.y);
    CMUL(v2, s0b0.z, s0b0.w);
    CMUL(v4, s0b1.x, s0b1.y);
    CMUL(v6, s0b1.z, s0b1.w);

    // --- output rows jj = 4t..4t+3: MMI_OUT pair reduce, then e^{i th_out} ---
#define OUTP(va, vb, jj) do { \
        float _ox = fmaf(AMP_, (va).x, -AMQ_ * (vb).y); \
        float _oy = fmaf(AMP_, (va).y,  AMQ_ * (vb).x); \
        float _so, _co; sincosf(theta_out[jj], &_so, &_co); \
        float _re = _ox * _co - _oy * _so; \
        float _im = _ox * _so + _oy * _co; \
        if (mode == 1) { out[(jj) * NCOLS + c] = _re; } \
        else { out[(jj) * NCOLS + c] = _re; \
               out[NCOLS * NCOLS + (jj) * NCOLS + c] = _im; } } while (0)

    OUTP(v0, v1, 4 * t);
    OUTP(v2, v3, 4 * t + 1);
    OUTP(v4, v5, 4 * t + 2);
    OUTP(v6, v7, 4 * t + 3);
#undef OUTP
}

extern "C" void kernel_launch(void* const* d_in, const int* in_sizes, int n_in,
                              void* d_out, int out_size) {
    // Inputs identified by SIZE (theta_even = unique 32640-elem array;
    // theta_in precedes theta_out).
    const float* th_ev  = nullptr;
    const float* small_[2] = {nullptr, nullptr};
    int ns = 0;
    for (int i = 0; i < n_in && i < 3; i++) {
        if (in_sizes[i] > 1000) th_ev = (const float*)d_in[i];
        else if (ns < 2)        small_[ns++] = (const float*)d_in[i];
    }
    const float* th_in  = small_[0];
    const float* th_out = small_[1];

    int mode = (out_size == NCOLS * NCOLS) ? 1 : 2;  // 16384 -> real-only, else planar

    phase_kernel<<<(NLAYERS * NCOLS + 255) / 256, 256>>>(th_ev);
    mesh_kernel<<<NCOLS, 32>>>(th_in, th_out, (float*)d_out, mode);
}